// round 17
// baseline (speedup 1.0000x reference)
#include <cuda_runtime.h>
#include <cuda_bf16.h>
#include <cstdint>

// NCE loss (training branch, size_average=True).
// N=4096, E=1024, V=50257, K=25.
// EXPERIMENT: weight gather via TMA bulk copy (cp.async.bulk, 1 instr / 4KB
// row) instead of 256 per-lane LDGs -- tests whether the LSU/L1tex request
// path (not the memory fabric) is the residual binder.
// Per warp: 2-slot x 4KB SMEM ring + per-slot mbarrier; elected-lane issue,
// acquire-parity wait, conflict-free float4 LDS compute, refill-after-use.
// Persistent grid 444 CTAs (3/SM x 148), 256 thr. x double-buffered via
// cp.async. Epilogue: one atomicAdd per CTA (d_out zeroed by memset node).

#define THREADS   256
#define NWARP     8
#define CTAS_SM   3
#define GRID      (148 * CTAS_SM)          // 444
#define ROW_BYTES 4096
#define WOFF      0                        // weight slots: 8 warps * 2 * 4KB
#define XOFF      (NWARP * 2 * ROW_BYTES)  // 64KB
#define SMEM_DYN  (XOFF + 2 * ROW_BYTES)   // 72KB

__device__ __forceinline__ void cp16(uint32_t dst, const void* src) {
    asm volatile("cp.async.cg.shared.global [%0], [%1], 16;\n" :: "r"(dst), "l"(src));
}
__device__ __forceinline__ void cp_commit() {
    asm volatile("cp.async.commit_group;\n" ::: "memory");
}
__device__ __forceinline__ uint32_t s2u(const void* p) {
    uint32_t a;
    asm("{ .reg .u64 t; cvta.to.shared.u64 t, %1; cvt.u32.u64 %0, t; }" : "=r"(a) : "l"(p));
    return a;
}
__device__ __forceinline__ void mbar_init(uint32_t mbar, uint32_t cnt) {
    asm volatile("mbarrier.init.shared.b64 [%0], %1;" :: "r"(mbar), "r"(cnt) : "memory");
}
__device__ __forceinline__ void mbar_expect_tx(uint32_t mbar, uint32_t bytes) {
    asm volatile("mbarrier.arrive.expect_tx.shared.b64 _, [%0], %1;"
                 :: "r"(mbar), "r"(bytes) : "memory");
}
__device__ __forceinline__ void mbar_wait(uint32_t mbar, uint32_t phase) {
    asm volatile(
        "{\n\t.reg .pred P;\n\t"
        "W_%=:\n\t"
        "mbarrier.try_wait.parity.acquire.cta.shared::cta.b64 P, [%0], %1, 0x989680;\n\t"
        "@!P bra W_%=;\n\t"
        "}" :: "r"(mbar), "r"(phase) : "memory");
}
__device__ __forceinline__ void bulk_row(uint32_t dst, const void* src, uint32_t mbar) {
    asm volatile(
        "cp.async.bulk.shared::cta.global.mbarrier::complete_tx::bytes [%0], [%1], %2, [%3];"
        :: "r"(dst), "l"(src), "r"((uint32_t)ROW_BYTES), "r"(mbar) : "memory");
}

__global__ __launch_bounds__(THREADS, CTAS_SM)
void nce_main(const float* __restrict__ x,
              const int*   __restrict__ target,
              const int*   __restrict__ noise_idx,
              const float* __restrict__ weight,
              const float* __restrict__ bias,
              const float* __restrict__ noise,
              float* __restrict__ out,
              int N, int E, int K)
{
    extern __shared__ char dyn[];
    __shared__ unsigned long long mbar_s[NWARP * 2];
    __shared__ float wloss[NWARP];

    const int tid  = threadIdx.x;
    const int lane = tid & 31;
    const int wid  = tid >> 5;

    const uint32_t dynb  = s2u(dyn);
    const uint32_t wbase = dynb + WOFF + wid * (2 * ROW_BYTES);
    const uint32_t mb0   = s2u(&mbar_s[wid * 2]);
    const uint32_t mb1   = mb0 + 8;

    if (tid < NWARP * 2) mbar_init(s2u(&mbar_s[tid]), 1);

    // Prime x buffer 0
    const int n0 = blockIdx.x;
    const int nrows = (n0 < N) ? ((N - 1 - n0) / GRID + 1) : 0;
    if (n0 < N)
        cp16(dynb + XOFF + tid * 16, (const char*)(x + (size_t)n0 * E) + tid * 16);
    cp_commit();
    __syncthreads();                         // mbar init visible

    // This warp's k set: cw dots per row (warps 0,1 own 4; others 3)
    const int cw = 3 + (wid < 2);

    // Prefetch cursor (pr, pjj) and linear count pj; idx queue mirrors slots.
    int pr = 0, pjj = 0, pj = 0;
    int idxq[2];
    auto doPrefetch = [&]() {
        if (pr < nrows) {
            const int n  = n0 + pr * GRID;
            const int kk = wid + 8 * pjj;
            const int idx = (kk == 0) ? __ldg(&target[n])
                                      : __ldg(&noise_idx[n * K + (kk - 1)]);
            const int slot = pj & 1;
            idxq[slot] = idx;
            if (lane == 0) {
                const uint32_t mb = slot ? mb1 : mb0;
                mbar_expect_tx(mb, ROW_BYTES);
                bulk_row(wbase + slot * ROW_BYTES, weight + (size_t)idx * E, mb);
            }
            pj++; if (++pjj == cw) { pjj = 0; pr++; }
        }
    };
    doPrefetch();                            // prime slot 0 (dot 0)

    float loss = 0.0f;
    int   cj = 0;                            // consume counter
    int   ph[2] = {0, 0};                    // per-slot mbar phase
    int   xbuf = 0;

    for (int r = 0, n = n0; r < nrows; r++, n += GRID) {
        // Stream next row's x into the other buffer; wait for this row's x.
        const int n_next = n + GRID;
        if (r + 1 < nrows) {
            cp16(dynb + XOFF + (xbuf ^ 1) * ROW_BYTES + tid * 16,
                 (const char*)(x + (size_t)n_next * E) + tid * 16);
            cp_commit();
            asm volatile("cp.async.wait_group 1;\n" ::: "memory");
        } else {
            asm volatile("cp.async.wait_group 0;\n" ::: "memory");
        }
        __syncthreads();

        const float4* xb = reinterpret_cast<const float4*>(dyn + XOFF + xbuf * ROW_BYTES);

        for (int jj = 0; jj < cw; jj++, cj++) {
            const int slot = cj & 1;
            const int kk   = wid + 8 * jj;
            const int idx  = idxq[slot];

            // Wait for this slot's bulk copy (acquire orders the SMEM data)
            mbar_wait(slot ? mb1 : mb0, ph[slot]);
            ph[slot] ^= 1;

            const float4* wb = reinterpret_cast<const float4*>(
                dyn + WOFF + wid * (2 * ROW_BYTES) + slot * ROW_BYTES);

            float s = 0.0f;
            #pragma unroll
            for (int j = 0; j < 8; j++) {    // conflict-free float4 LDS
                const float4 wv = wb[lane + 32 * j];
                const float4 xv = xb[lane + 32 * j];
                s += wv.x * xv.x + wv.y * xv.y + wv.z * xv.z + wv.w * xv.w;
            }

            // All lanes done reading the slot before the async refill writes it
            __syncwarp();
            asm volatile("fence.proxy.async.shared::cta;" ::: "memory");
            doPrefetch();                    // refill this slot for dot cj+2

            #pragma unroll
            for (int o = 16; o; o >>= 1)
                s += __shfl_xor_sync(0xffffffffu, s, o);

            if (lane == 0) {
                const float logit = s + __ldg(&bias[idx]);
                const float p     = __expf(logit - 9.0f);
                const float kpn   = 25.0f * __ldg(&noise[idx]);
                const float num   = (kk == 0) ? p : kpn;
                loss += __logf(num / (p + kpn));
            }
        }
        xbuf ^= 1;
        __syncthreads();                     // x buffer fully consumed
    }

    if (lane == 0) wloss[wid] = loss;
    __syncthreads();
    if (tid == 0) {
        float t = 0.0f;
        #pragma unroll
        for (int w = 0; w < NWARP; w++) t += wloss[w];
        atomicAdd(out, -t / (float)N);       // one atomic per CTA
    }
}

extern "C" void kernel_launch(void* const* d_in, const int* in_sizes, int n_in,
                              void* d_out, int out_size)
{
    const float* x         = (const float*)d_in[0];
    const int*   target    = (const int*)  d_in[1];
    const int*   noise_idx = (const int*)  d_in[2];
    const float* weight    = (const float*)d_in[3];
    const float* bias      = (const float*)d_in[4];
    const float* noise     = (const float*)d_in[5];

    const int N = in_sizes[1];            // 4096
    const int E = in_sizes[0] / N;        // 1024
    const int K = in_sizes[2] / N;        // 25

    static int smem_set = 0;
    if (!smem_set) {
        cudaFuncSetAttribute(nce_main, cudaFuncAttributeMaxDynamicSharedMemorySize,
                             SMEM_DYN);
        smem_set = 1;
    }

    cudaMemsetAsync(d_out, 0, sizeof(float));
    nce_main<<<GRID, THREADS, SMEM_DYN>>>(x, target, noise_idx, weight, bias, noise,
                                          (float*)d_out, N, E, K);
}